// round 16
// baseline (speedup 1.0000x reference)
#include <cuda_runtime.h>
#include <cstdint>

// ---------------- problem constants ----------------
#define B_      128
#define T_IN_   240
#define T_OUT_  30
#define D_      128
#define H_      256
#define G3_     768

#define ENC_LEN 30720   // T_IN * B
#define DEC_LEN 3840    // T_OUT * B

// segmentation: 6 chains per 4-CTA cluster, 2 pipelined groups of 3
#define CHAINS   6
#define GCH      3       // chains per group
#define CHUNK    160     // 192 enc chains * 160 = 30720 ; 24 dec chains * 160 = 3840
#define WARMUP   48
#define STEPS    (CHUNK + WARMUP)   // 208
#define NCL_ENC  32
#define NCL_DEC  4

#define NTHREADS 384     // 12 warps; every thread is one gate (c,j)

// ---------------- device scratch ----------------
__device__ float g_gi_enc[(size_t)ENC_LEN * G3_];   // ~94 MB
__device__ float g_gi_dec[(size_t)DEC_LEN * G3_];   // ~12 MB

// ---------------- helpers ----------------
__device__ __forceinline__ uint32_t smem_u32(const void* p) {
    return (uint32_t)__cvta_generic_to_shared(p);
}
__device__ __forceinline__ uint32_t mapa_u32(uint32_t addr, uint32_t rank) {
    uint32_t d;
    asm("mapa.shared::cluster.u32 %0, %1, %2;" : "=r"(d) : "r"(addr), "r"(rank));
    return d;
}
__device__ __forceinline__ void cl_sync() {
    asm volatile("barrier.cluster.arrive.aligned;" ::: "memory");
    asm volatile("barrier.cluster.wait.aligned;"   ::: "memory");
}
__device__ __forceinline__ void mbar_init(uint32_t mbar, uint32_t count) {
    asm volatile("mbarrier.init.shared.b64 [%0], %1;" :: "r"(mbar), "r"(count) : "memory");
}
__device__ __forceinline__ void mbar_arrive_expect(uint32_t mbar, uint32_t bytes) {
    asm volatile("mbarrier.arrive.expect_tx.shared::cta.b64 _, [%0], %1;"
                 :: "r"(mbar), "r"(bytes) : "memory");
}
__device__ __forceinline__ void mbar_wait_parity(uint32_t mbar, uint32_t parity) {
    uint32_t done;
    asm volatile(
        "{\n\t.reg .pred p;\n\t"
        "mbarrier.try_wait.parity.acquire.cta.shared::cta.b64 p, [%1], %2;\n\t"
        "selp.b32 %0, 1, 0, p;\n\t}"
        : "=r"(done) : "r"(mbar), "r"(parity) : "memory");
    if (!done) {
        asm volatile(
            "{\n\t.reg .pred P1;\n\t"
            "WAIT_LOOP_%=:\n\t"
            "mbarrier.try_wait.parity.acquire.cta.shared::cta.b64 P1, [%0], %1, 0x989680;\n\t"
            "@P1 bra.uni WAIT_DONE_%=;\n\t"
            "bra.uni WAIT_LOOP_%=;\n\t"
            "WAIT_DONE_%=:\n\t}"
            :: "r"(mbar), "r"(parity) : "memory");
    }
}
__device__ __forceinline__ void st_async_f32(uint32_t addr, float v, uint32_t mbar) {
    asm volatile(
        "st.async.weak.shared::cluster.mbarrier::complete_tx::bytes.f32 [%0], %1, [%2];"
        :: "r"(addr), "f"(v), "r"(mbar) : "memory");
}
__device__ __forceinline__ unsigned long long ffma2(unsigned long long a,
                                                    unsigned long long b,
                                                    unsigned long long c) {
    unsigned long long r;
    asm("fma.rn.f32x2 %0, %1, %2, %3;" : "=l"(r) : "l"(a), "l"(b), "l"(c));
    return r;
}
__device__ __forceinline__ unsigned long long dup2(float v) {
    unsigned long long r;
    asm("mov.b64 %0, {%1, %1};" : "=l"(r) : "f"(v));
    return r;
}
__device__ __forceinline__ float f2lo(unsigned long long v) {
    return __uint_as_float((unsigned)(v & 0xffffffffull));
}
__device__ __forceinline__ float f2hi(unsigned long long v) {
    return __uint_as_float((unsigned)(v >> 32));
}
__device__ __forceinline__ float tanh_ap(float x) {
    float y;
    asm("tanh.approx.f32 %0, %1;" : "=f"(y) : "f"(x));
    return y;
}
__device__ __forceinline__ float sig_(float x) { return 0.5f * tanh_ap(0.5f * x) + 0.5f; }
__device__ __forceinline__ float th_(float x)  { return tanh_ap(x); }

// ============================================================
// Phase 1: GI = X @ Wih^T + bih — PACK-FREE f32x2 micro-kernel.
// X tile stored as duplicated pairs in SMEM (Xs2[k][pos]=(x,x));
// W tile read as adjacent gate-pairs (ulonglong2 view).
// Inner loop per k: 3 LDS.128 + 8 FFMA2, ZERO packs.
// acc2[pos][gate-pair]: lane lo = gate 2jp, hi = gate 2jp+1.
// SMEM = 32KB (Xs2) + 16KB (Ws) = 48KB exactly.
// ============================================================
__global__ __launch_bounds__(256)
void gi_gemm(const float* __restrict__ x,
             const float* __restrict__ Wih_e, const float* __restrict__ bih_e,
             const float* __restrict__ Wih_d, const float* __restrict__ bih_d)
{
    __shared__ __align__(16) unsigned long long Xs2[64][64];  // [k][pos] dup pairs
    __shared__ __align__(16) float Ws[64][64];                // [k][gate]

    const int tileP = blockIdx.x;
    const bool enc = (tileP < (ENC_LEN / 64));
    const float* __restrict__ Wih = enc ? Wih_e : Wih_d;
    const float* __restrict__ bih = enc ? bih_e : bih_d;
    float* __restrict__ gout = enc ? g_gi_enc : g_gi_dec;
    const int p0 = (enc ? tileP : (tileP - ENC_LEN / 64)) * 64;
    const int g0 = blockIdx.y * 64;
    const int tid = threadIdx.x;
    const int tstride = enc ? 1 : 8;

    const int tx = tid & 15;      // gate quad
    const int ty = tid >> 4;      // pos quad
    unsigned long long acc2[4][2] = {};   // [pos][gate-pair]

    for (int kc = 0; kc < 2; ++kc) {
        #pragma unroll
        for (int i = tid; i < 64 * 64; i += 256) {
            int pos = i >> 6, k = i & 63;
            int p = p0 + pos;
            int b = p & 127, t = (p >> 7) * tstride;
            Xs2[k][pos] = dup2(x[((size_t)b * T_IN_ + t) * D_ + kc * 64 + k]);
        }
        #pragma unroll
        for (int i = tid; i < 64 * 64; i += 256) {
            int g = i >> 6, k = i & 63;
            Ws[k][g] = Wih[(size_t)(g0 + g) * D_ + kc * 64 + k];
        }
        __syncthreads();

        #pragma unroll 8
        for (int k = 0; k < 64; ++k) {
            ulonglong2 a01 = *(const ulonglong2*)&Xs2[k][ty * 4];
            ulonglong2 a23 = *(const ulonglong2*)&Xs2[k][ty * 4 + 2];
            ulonglong2 b01 = *(const ulonglong2*)&Ws[k][tx * 4];
            acc2[0][0] = ffma2(a01.x, b01.x, acc2[0][0]);
            acc2[0][1] = ffma2(a01.x, b01.y, acc2[0][1]);
            acc2[1][0] = ffma2(a01.y, b01.x, acc2[1][0]);
            acc2[1][1] = ffma2(a01.y, b01.y, acc2[1][1]);
            acc2[2][0] = ffma2(a23.x, b01.x, acc2[2][0]);
            acc2[2][1] = ffma2(a23.x, b01.y, acc2[2][1]);
            acc2[3][0] = ffma2(a23.y, b01.x, acc2[3][0]);
            acc2[3][1] = ffma2(a23.y, b01.y, acc2[3][1]);
        }
        __syncthreads();
    }

    float bz[4];
    #pragma unroll
    for (int j = 0; j < 4; ++j) bz[j] = bih[g0 + tx * 4 + j];

    #pragma unroll
    for (int i = 0; i < 4; ++i) {
        int p = p0 + ty * 4 + i;
        float4 o;
        o.x = f2lo(acc2[i][0]) + bz[0];
        o.y = f2hi(acc2[i][0]) + bz[1];
        o.z = f2lo(acc2[i][1]) + bz[2];
        o.w = f2hi(acc2[i][1]) + bz[3];
        *(float4*)&gout[(size_t)p * G3_ + g0 + tx * 4] = o;
    }
}

// ============================================================
// Phase 2: segmented GRU scan — 6 chains in 2 pipelined groups.
// (identical to R15 proven kernel; only WARMUP changed 64->48)
// ============================================================
__global__ __launch_bounds__(NTHREADS, 1) __cluster_dims__(4, 1, 1)
void gru_scan(const float* __restrict__ Whh_e, const float* __restrict__ bhh_e,
              const float* __restrict__ Whh_d, const float* __restrict__ bhh_d,
              float* __restrict__ out)
{
    __shared__ __align__(16) float hbuf[2][CHAINS][256];   // [parity][chain][H]
    __shared__ float sGHp[CHAINS][4][192];                 // [chain][quarter][row]
    __shared__ float sBH[192];
    __shared__ __align__(8) unsigned long long mbars[2][2]; // [group][parity]

    const int tid  = threadIdx.x;
    const int warp = tid >> 5;
    const int lane = tid & 31;
    uint32_t rank;
    asm("mov.u32 %0, %%cluster_ctarank;" : "=r"(rank));

    const int cl   = blockIdx.x >> 2;
    const bool enc = cl < NCL_ENC;
    const int lcl  = enc ? cl : cl - NCL_ENC;
    const float* __restrict__ Whh = enc ? Whh_e : Whh_d;
    const float* __restrict__ bhh = enc ? bhh_e : bhh_d;
    const float* __restrict__ gi  = enc ? g_gi_enc : g_gi_dec;

    const uint32_t mb_base = smem_u32(&mbars[0][0]);
    // mbar addr: mb_base + (group*2 + parity)*8

    // ---- shared init ----
    for (int i = tid; i < 2 * CHAINS * 256; i += NTHREADS)
        ((float*)hbuf)[i] = 0.0f;
    if (tid < 192) {
        int g = tid >> 6, j = tid & 63;
        sBH[tid] = bhh[g * 256 + (int)rank * 64 + j];
    }
    if (tid == 0) {
        #pragma unroll
        for (int i = 0; i < 4; ++i) mbar_init(mb_base + i * 8, 1);
        // pre-arm parity-1 barriers of both groups (step-0 stores land there)
        mbar_arrive_expect(mb_base + (0 * 2 + 1) * 8, 1024 * GCH);
        mbar_arrive_expect(mb_base + (1 * 2 + 1) * 8, 1024 * GCH);
    }
    __syncthreads();
    cl_sync();   // barriers + zeroed buffers visible cluster-wide

    // ---- matvec mapping: 2 rows x one k-quarter ----
    const int q  = warp & 3;            // k-quarter 0..3
    const int g  = warp >> 2;           // row-group 0..2
    const int r0 = g * 32 + lane;       // 0..95
    const int r1 = r0 + 96;             // 96..191
    const int Rg0 = (r0 >> 6) * 256 + (int)rank * 64 + (r0 & 63);
    const int Rg1 = (r1 >> 6) * 256 + (int)rank * 64 + (r1 & 63);

    // 2 x 64 weights in registers (64 packed f32x2 total)
    unsigned long long wA[32], wB[32];
    {
        const ulonglong2* w0 = (const ulonglong2*)(Whh + (size_t)Rg0 * H_ + q * 64);
        const ulonglong2* w1 = (const ulonglong2*)(Whh + (size_t)Rg1 * H_ + q * 64);
        #pragma unroll
        for (int i = 0; i < 16; ++i) {
            ulonglong2 t0 = w0[i];
            wA[2 * i] = t0.x; wA[2 * i + 1] = t0.y;
            ulonglong2 t1 = w1[i];
            wB[2 * i] = t1.x; wB[2 * i + 1] = t1.y;
        }
    }

    // ---- gate mapping: one (chain, coord) per thread ----
    const int gc = tid >> 6;            // chain 0..5 (group = gc/3)
    const int gj = tid & 63;            // coord 0..63
    const int ggrp = (gc >= GCH) ? 1 : 0;
    const int gbase = (lcl * CHAINS + gc) * CHUNK;
    const int goff  = (int)rank * 64 + gj;
    const float* gpt;
    {
        int p0 = gbase - WARMUP; if (p0 < 0) p0 = 0;
        gpt = gi + (size_t)p0 * G3_ + goff;
    }

    // peer addresses
    uint32_t peer_hb[4], peer_mb[4];
    {
        uint32_t my_hb = smem_u32(&hbuf[0][0][0]);
        #pragma unroll
        for (int r = 0; r < 4; ++r) {
            peer_hb[r] = mapa_u32(my_hb, r);
            peer_mb[r] = mapa_u32(mb_base, r);
        }
    }

    uint32_t mph[2][2] = {{0u, 0u}, {0u, 0u}};

    for (int s = 0; s < STEPS; ++s) {
        const int ph = s & 1;

        // gi loads for THIS step (issued before the waits: hidden)
        float gv0 = __ldg(gpt);
        float gv1 = __ldg(gpt + 256);
        float gv2 = __ldg(gpt + 512);
        if (gbase + s + 1 > WARMUP) gpt += G3_;

        // ================= two pipelined groups =================
        #pragma unroll
        for (int grp = 0; grp < 2; ++grp) {
            const uint32_t mb = mb_base + (uint32_t)(grp * 2 + ph) * 8u;

            // wait for this group's h(s)
            if (s > 0) {
                mbar_wait_parity(mb, mph[grp][ph] & 1u);
                mph[grp][ph]++;
            }
            // arm for step (s+1)'s stores — after the wait (proven ordering)
            if (tid == 0 && s + 1 < STEPS)
                mbar_arrive_expect(mb, 1024 * GCH);

            // matvec for this group's 3 chains
            #pragma unroll
            for (int ci = 0; ci < GCH; ++ci) {
                const int c = grp * GCH + ci;
                const ulonglong2* h2 =
                    (const ulonglong2*)(&hbuf[ph][c][0]) + q * 16;
                unsigned long long a = 0ull, b = 0ull;
                #pragma unroll
                for (int i = 0; i < 16; ++i) {
                    ulonglong2 hv = h2[i];        // 1 LDS.128 -> 4 FFMA2
                    a = ffma2(wA[2 * i],     hv.x, a);
                    a = ffma2(wA[2 * i + 1], hv.y, a);
                    b = ffma2(wB[2 * i],     hv.x, b);
                    b = ffma2(wB[2 * i + 1], hv.y, b);
                }
                sGHp[c][q][r0] = f2lo(a) + f2hi(a);
                sGHp[c][q][r1] = f2lo(b) + f2hi(b);
            }
            __syncthreads();   // group partials visible; arm before stores

            // gates for this group: threads whose chain is in the group
            if (ggrp == grp) {
                const int p = gbase + s - WARMUP;

                float ghr = sGHp[gc][0][gj]       + sGHp[gc][1][gj]
                          + sGHp[gc][2][gj]       + sGHp[gc][3][gj]       + sBH[gj];
                float ghz = sGHp[gc][0][64 + gj]  + sGHp[gc][1][64 + gj]
                          + sGHp[gc][2][64 + gj]  + sGHp[gc][3][64 + gj]  + sBH[64 + gj];
                float ghn = sGHp[gc][0][128 + gj] + sGHp[gc][1][128 + gj]
                          + sGHp[gc][2][128 + gj] + sGHp[gc][3][128 + gj] + sBH[128 + gj];
                float r_ = sig_(gv0 + ghr);
                float z_ = sig_(gv1 + ghz);
                float n_ = th_ (gv2 + r_ * ghn);
                float hold = hbuf[ph][gc][goff];
                float hn = (1.0f - z_) * n_ + z_ * hold;
                if (p < 0) hn = 0.0f;   // pre-sequence region of chain 0

                if (s + 1 < STEPS) {
                    uint32_t boff = (uint32_t)(((ph ^ 1) * CHAINS + gc) * 256 + goff) * 4u;
                    uint32_t moff = (uint32_t)(grp * 2 + (ph ^ 1)) * 8u;
                    #pragma unroll
                    for (int r = 0; r < 4; ++r)
                        st_async_f32(peer_hb[r] + boff, hn, peer_mb[r] + moff);
                }

                if (s >= WARMUP) {
                    if (enc) {
                        if ((p & 127) == 127) {
                            int t_out = p >> 7;
                            out[(size_t)t_out * H_ + goff] = hn;
                        }
                    } else {
                        int b = p & 127, t = p >> 7;
                        out[(size_t)(T_IN_ * H_) +
                            ((size_t)b * T_OUT_ + t) * H_ + goff] = hn;
                    }
                }
            }
            // sGHp WAR across steps: this group's next-step matvec writes
            // are separated from these reads by the other group's
            // syncthreads (this step) + this group's wait (next step).
        }
    }

    cl_sync();   // drain async traffic before cluster teardown
}

// ============================================================
// launch
// ============================================================
extern "C" void kernel_launch(void* const* d_in, const int* in_sizes, int n_in,
                              void* d_out, int out_size)
{
    const float* x     = (const float*)d_in[0];
    const float* Wih_e = (const float*)d_in[1];
    const float* Whh_e = (const float*)d_in[2];
    const float* bih_e = (const float*)d_in[3];
    const float* bhh_e = (const float*)d_in[4];
    const float* Wih_d = (const float*)d_in[5];
    const float* Whh_d = (const float*)d_in[6];
    const float* bih_d = (const float*)d_in[7];
    const float* bhh_d = (const float*)d_in[8];
    float* out = (float*)d_out;

    dim3 ggrid(ENC_LEN / 64 + DEC_LEN / 64, G3_ / 64);  // (540, 12)
    gi_gemm<<<ggrid, 256>>>(x, Wih_e, bih_e, Wih_d, bih_d);

    gru_scan<<<(NCL_ENC + NCL_DEC) * 4, NTHREADS>>>(
        Whh_e, bhh_e, Whh_d, bhh_d, out);
}

// round 17
// speedup vs baseline: 1.5492x; 1.5492x over previous
#include <cuda_runtime.h>
#include <cstdint>

// ---------------- problem constants ----------------
#define B_      128
#define T_IN_   240
#define T_OUT_  30
#define D_      128
#define H_      256
#define G3_     768

#define ENC_LEN 30720   // T_IN * B
#define DEC_LEN 3840    // T_OUT * B

// segmentation: 6 chains per 4-CTA cluster, 2 pipelined groups of 3
#define CHAINS   6
#define GCH      3       // chains per group
#define CHUNK    160     // 192 enc chains * 160 = 30720 ; 24 dec chains * 160 = 3840
#define WARMUP   48
#define STEPS    (CHUNK + WARMUP)   // 208
#define NCL_ENC  32
#define NCL_DEC  4

#define NTHREADS 384     // 12 warps; every thread is one gate (c,j)

// ---------------- device scratch ----------------
__device__ float g_gi_enc[(size_t)ENC_LEN * G3_];   // ~94 MB
__device__ float g_gi_dec[(size_t)DEC_LEN * G3_];   // ~12 MB

// ---------------- helpers ----------------
__device__ __forceinline__ uint32_t smem_u32(const void* p) {
    return (uint32_t)__cvta_generic_to_shared(p);
}
__device__ __forceinline__ uint32_t mapa_u32(uint32_t addr, uint32_t rank) {
    uint32_t d;
    asm("mapa.shared::cluster.u32 %0, %1, %2;" : "=r"(d) : "r"(addr), "r"(rank));
    return d;
}
__device__ __forceinline__ void cl_sync() {
    asm volatile("barrier.cluster.arrive.aligned;" ::: "memory");
    asm volatile("barrier.cluster.wait.aligned;"   ::: "memory");
}
__device__ __forceinline__ void mbar_init(uint32_t mbar, uint32_t count) {
    asm volatile("mbarrier.init.shared.b64 [%0], %1;" :: "r"(mbar), "r"(count) : "memory");
}
__device__ __forceinline__ void mbar_arrive_expect(uint32_t mbar, uint32_t bytes) {
    asm volatile("mbarrier.arrive.expect_tx.shared::cta.b64 _, [%0], %1;"
                 :: "r"(mbar), "r"(bytes) : "memory");
}
__device__ __forceinline__ void mbar_wait_parity(uint32_t mbar, uint32_t parity) {
    uint32_t done;
    asm volatile(
        "{\n\t.reg .pred p;\n\t"
        "mbarrier.try_wait.parity.acquire.cta.shared::cta.b64 p, [%1], %2;\n\t"
        "selp.b32 %0, 1, 0, p;\n\t}"
        : "=r"(done) : "r"(mbar), "r"(parity) : "memory");
    if (!done) {
        asm volatile(
            "{\n\t.reg .pred P1;\n\t"
            "WAIT_LOOP_%=:\n\t"
            "mbarrier.try_wait.parity.acquire.cta.shared::cta.b64 P1, [%0], %1, 0x989680;\n\t"
            "@P1 bra.uni WAIT_DONE_%=;\n\t"
            "bra.uni WAIT_LOOP_%=;\n\t"
            "WAIT_DONE_%=:\n\t}"
            :: "r"(mbar), "r"(parity) : "memory");
    }
}
__device__ __forceinline__ void st_async_f32(uint32_t addr, float v, uint32_t mbar) {
    asm volatile(
        "st.async.weak.shared::cluster.mbarrier::complete_tx::bytes.f32 [%0], %1, [%2];"
        :: "r"(addr), "f"(v), "r"(mbar) : "memory");
}
__device__ __forceinline__ unsigned long long ffma2(unsigned long long a,
                                                    unsigned long long b,
                                                    unsigned long long c) {
    unsigned long long r;
    asm("fma.rn.f32x2 %0, %1, %2, %3;" : "=l"(r) : "l"(a), "l"(b), "l"(c));
    return r;
}
__device__ __forceinline__ float f2lo(unsigned long long v) {
    return __uint_as_float((unsigned)(v & 0xffffffffull));
}
__device__ __forceinline__ float f2hi(unsigned long long v) {
    return __uint_as_float((unsigned)(v >> 32));
}
__device__ __forceinline__ float tanh_ap(float x) {
    float y;
    asm("tanh.approx.f32 %0, %1;" : "=f"(y) : "f"(x));
    return y;
}
__device__ __forceinline__ float sig_(float x) { return 0.5f * tanh_ap(0.5f * x) + 0.5f; }
__device__ __forceinline__ float th_(float x)  { return tanh_ap(x); }

// ============================================================
// Phase 1: GI = X @ Wih^T + bih — scalar FFMA, padded [64][68]
// tiles (conflict-free). PROVEN form: ~190-197 us in R13/R14.
// ============================================================
__global__ __launch_bounds__(256)
void gi_gemm(const float* __restrict__ x,
             const float* __restrict__ Wih_e, const float* __restrict__ bih_e,
             const float* __restrict__ Wih_d, const float* __restrict__ bih_d)
{
    __shared__ float Xs[64][68];   // [k][pos]
    __shared__ float Ws[64][68];   // [k][gate]

    const int tileP = blockIdx.x;
    const bool enc = (tileP < (ENC_LEN / 64));
    const float* __restrict__ Wih = enc ? Wih_e : Wih_d;
    const float* __restrict__ bih = enc ? bih_e : bih_d;
    float* __restrict__ gout = enc ? g_gi_enc : g_gi_dec;
    const int p0 = (enc ? tileP : (tileP - ENC_LEN / 64)) * 64;
    const int g0 = blockIdx.y * 64;
    const int tid = threadIdx.x;
    const int tstride = enc ? 1 : 8;

    const int tx = tid & 15;
    const int ty = tid >> 4;
    float acc[4][4] = {};

    for (int kc = 0; kc < 2; ++kc) {
        #pragma unroll
        for (int i = tid; i < 64 * 64; i += 256) {
            int pos = i >> 6, k = i & 63;
            int p = p0 + pos;
            int b = p & 127, t = (p >> 7) * tstride;
            Xs[k][pos] = x[((size_t)b * T_IN_ + t) * D_ + kc * 64 + k];
        }
        #pragma unroll
        for (int i = tid; i < 64 * 64; i += 256) {
            int g = i >> 6, k = i & 63;
            Ws[k][g] = Wih[(size_t)(g0 + g) * D_ + kc * 64 + k];
        }
        __syncthreads();

        #pragma unroll 16
        for (int k = 0; k < 64; ++k) {
            float4 a = *(const float4*)&Xs[k][ty * 4];
            float4 b = *(const float4*)&Ws[k][tx * 4];
            float av[4] = {a.x, a.y, a.z, a.w};
            float bv[4] = {b.x, b.y, b.z, b.w};
            #pragma unroll
            for (int i = 0; i < 4; ++i)
                #pragma unroll
                for (int j = 0; j < 4; ++j)
                    acc[i][j] = fmaf(av[i], bv[j], acc[i][j]);
        }
        __syncthreads();
    }

    float bz[4];
    #pragma unroll
    for (int j = 0; j < 4; ++j) bz[j] = bih[g0 + tx * 4 + j];

    #pragma unroll
    for (int i = 0; i < 4; ++i) {
        int p = p0 + ty * 4 + i;
        float4 o;
        o.x = acc[i][0] + bz[0];
        o.y = acc[i][1] + bz[1];
        o.z = acc[i][2] + bz[2];
        o.w = acc[i][3] + bz[3];
        *(float4*)&gout[(size_t)p * G3_ + g0 + tx * 4] = o;
    }
}

// ============================================================
// Phase 2: segmented GRU scan — 6 chains in 2 pipelined groups.
// (byte-identical to R16's proven scan; WARMUP=48)
// ============================================================
__global__ __launch_bounds__(NTHREADS, 1) __cluster_dims__(4, 1, 1)
void gru_scan(const float* __restrict__ Whh_e, const float* __restrict__ bhh_e,
              const float* __restrict__ Whh_d, const float* __restrict__ bhh_d,
              float* __restrict__ out)
{
    __shared__ __align__(16) float hbuf[2][CHAINS][256];   // [parity][chain][H]
    __shared__ float sGHp[CHAINS][4][192];                 // [chain][quarter][row]
    __shared__ float sBH[192];
    __shared__ __align__(8) unsigned long long mbars[2][2]; // [group][parity]

    const int tid  = threadIdx.x;
    const int warp = tid >> 5;
    const int lane = tid & 31;
    uint32_t rank;
    asm("mov.u32 %0, %%cluster_ctarank;" : "=r"(rank));

    const int cl   = blockIdx.x >> 2;
    const bool enc = cl < NCL_ENC;
    const int lcl  = enc ? cl : cl - NCL_ENC;
    const float* __restrict__ Whh = enc ? Whh_e : Whh_d;
    const float* __restrict__ bhh = enc ? bhh_e : bhh_d;
    const float* __restrict__ gi  = enc ? g_gi_enc : g_gi_dec;

    const uint32_t mb_base = smem_u32(&mbars[0][0]);
    // mbar addr: mb_base + (group*2 + parity)*8

    // ---- shared init ----
    for (int i = tid; i < 2 * CHAINS * 256; i += NTHREADS)
        ((float*)hbuf)[i] = 0.0f;
    if (tid < 192) {
        int g = tid >> 6, j = tid & 63;
        sBH[tid] = bhh[g * 256 + (int)rank * 64 + j];
    }
    if (tid == 0) {
        #pragma unroll
        for (int i = 0; i < 4; ++i) mbar_init(mb_base + i * 8, 1);
        // pre-arm parity-1 barriers of both groups (step-0 stores land there)
        mbar_arrive_expect(mb_base + (0 * 2 + 1) * 8, 1024 * GCH);
        mbar_arrive_expect(mb_base + (1 * 2 + 1) * 8, 1024 * GCH);
    }
    __syncthreads();
    cl_sync();   // barriers + zeroed buffers visible cluster-wide

    // ---- matvec mapping: 2 rows x one k-quarter ----
    const int q  = warp & 3;            // k-quarter 0..3
    const int g  = warp >> 2;           // row-group 0..2
    const int r0 = g * 32 + lane;       // 0..95
    const int r1 = r0 + 96;             // 96..191
    const int Rg0 = (r0 >> 6) * 256 + (int)rank * 64 + (r0 & 63);
    const int Rg1 = (r1 >> 6) * 256 + (int)rank * 64 + (r1 & 63);

    // 2 x 64 weights in registers (64 packed f32x2 total)
    unsigned long long wA[32], wB[32];
    {
        const ulonglong2* w0 = (const ulonglong2*)(Whh + (size_t)Rg0 * H_ + q * 64);
        const ulonglong2* w1 = (const ulonglong2*)(Whh + (size_t)Rg1 * H_ + q * 64);
        #pragma unroll
        for (int i = 0; i < 16; ++i) {
            ulonglong2 t0 = w0[i];
            wA[2 * i] = t0.x; wA[2 * i + 1] = t0.y;
            ulonglong2 t1 = w1[i];
            wB[2 * i] = t1.x; wB[2 * i + 1] = t1.y;
        }
    }

    // ---- gate mapping: one (chain, coord) per thread ----
    const int gc = tid >> 6;            // chain 0..5 (group = gc/3)
    const int gj = tid & 63;            // coord 0..63
    const int ggrp = (gc >= GCH) ? 1 : 0;
    const int gbase = (lcl * CHAINS + gc) * CHUNK;
    const int goff  = (int)rank * 64 + gj;
    const float* gpt;
    {
        int p0 = gbase - WARMUP; if (p0 < 0) p0 = 0;
        gpt = gi + (size_t)p0 * G3_ + goff;
    }

    // peer addresses
    uint32_t peer_hb[4], peer_mb[4];
    {
        uint32_t my_hb = smem_u32(&hbuf[0][0][0]);
        #pragma unroll
        for (int r = 0; r < 4; ++r) {
            peer_hb[r] = mapa_u32(my_hb, r);
            peer_mb[r] = mapa_u32(mb_base, r);
        }
    }

    uint32_t mph[2][2] = {{0u, 0u}, {0u, 0u}};

    for (int s = 0; s < STEPS; ++s) {
        const int ph = s & 1;

        // gi loads for THIS step (issued before the waits: hidden)
        float gv0 = __ldg(gpt);
        float gv1 = __ldg(gpt + 256);
        float gv2 = __ldg(gpt + 512);
        if (gbase + s + 1 > WARMUP) gpt += G3_;

        // ================= two pipelined groups =================
        #pragma unroll
        for (int grp = 0; grp < 2; ++grp) {
            const uint32_t mb = mb_base + (uint32_t)(grp * 2 + ph) * 8u;

            // wait for this group's h(s)
            if (s > 0) {
                mbar_wait_parity(mb, mph[grp][ph] & 1u);
                mph[grp][ph]++;
            }
            // arm for step (s+1)'s stores — after the wait (proven ordering)
            if (tid == 0 && s + 1 < STEPS)
                mbar_arrive_expect(mb, 1024 * GCH);

            // matvec for this group's 3 chains
            #pragma unroll
            for (int ci = 0; ci < GCH; ++ci) {
                const int c = grp * GCH + ci;
                const ulonglong2* h2 =
                    (const ulonglong2*)(&hbuf[ph][c][0]) + q * 16;
                unsigned long long a = 0ull, b = 0ull;
                #pragma unroll
                for (int i = 0; i < 16; ++i) {
                    ulonglong2 hv = h2[i];        // 1 LDS.128 -> 4 FFMA2
                    a = ffma2(wA[2 * i],     hv.x, a);
                    a = ffma2(wA[2 * i + 1], hv.y, a);
                    b = ffma2(wB[2 * i],     hv.x, b);
                    b = ffma2(wB[2 * i + 1], hv.y, b);
                }
                sGHp[c][q][r0] = f2lo(a) + f2hi(a);
                sGHp[c][q][r1] = f2lo(b) + f2hi(b);
            }
            __syncthreads();   // group partials visible; arm before stores

            // gates for this group: threads whose chain is in the group
            if (ggrp == grp) {
                const int p = gbase + s - WARMUP;

                float ghr = sGHp[gc][0][gj]       + sGHp[gc][1][gj]
                          + sGHp[gc][2][gj]       + sGHp[gc][3][gj]       + sBH[gj];
                float ghz = sGHp[gc][0][64 + gj]  + sGHp[gc][1][64 + gj]
                          + sGHp[gc][2][64 + gj]  + sGHp[gc][3][64 + gj]  + sBH[64 + gj];
                float ghn = sGHp[gc][0][128 + gj] + sGHp[gc][1][128 + gj]
                          + sGHp[gc][2][128 + gj] + sGHp[gc][3][128 + gj] + sBH[128 + gj];
                float r_ = sig_(gv0 + ghr);
                float z_ = sig_(gv1 + ghz);
                float n_ = th_ (gv2 + r_ * ghn);
                float hold = hbuf[ph][gc][goff];
                float hn = (1.0f - z_) * n_ + z_ * hold;
                if (p < 0) hn = 0.0f;   // pre-sequence region of chain 0

                if (s + 1 < STEPS) {
                    uint32_t boff = (uint32_t)(((ph ^ 1) * CHAINS + gc) * 256 + goff) * 4u;
                    uint32_t moff = (uint32_t)(grp * 2 + (ph ^ 1)) * 8u;
                    #pragma unroll
                    for (int r = 0; r < 4; ++r)
                        st_async_f32(peer_hb[r] + boff, hn, peer_mb[r] + moff);
                }

                if (s >= WARMUP) {
                    if (enc) {
                        if ((p & 127) == 127) {
                            int t_out = p >> 7;
                            out[(size_t)t_out * H_ + goff] = hn;
                        }
                    } else {
                        int b = p & 127, t = p >> 7;
                        out[(size_t)(T_IN_ * H_) +
                            ((size_t)b * T_OUT_ + t) * H_ + goff] = hn;
                    }
                }
            }
            // sGHp WAR across steps: this group's next-step matvec writes
            // are separated from these reads by the other group's
            // syncthreads (this step) + this group's wait (next step).
        }
    }

    cl_sync();   // drain async traffic before cluster teardown
}

// ============================================================
// launch
// ============================================================
extern "C" void kernel_launch(void* const* d_in, const int* in_sizes, int n_in,
                              void* d_out, int out_size)
{
    const float* x     = (const float*)d_in[0];
    const float* Wih_e = (const float*)d_in[1];
    const float* Whh_e = (const float*)d_in[2];
    const float* bih_e = (const float*)d_in[3];
    const float* bhh_e = (const float*)d_in[4];
    const float* Wih_d = (const float*)d_in[5];
    const float* Whh_d = (const float*)d_in[6];
    const float* bih_d = (const float*)d_in[7];
    const float* bhh_d = (const float*)d_in[8];
    float* out = (float*)d_out;

    dim3 ggrid(ENC_LEN / 64 + DEC_LEN / 64, G3_ / 64);  // (540, 12)
    gi_gemm<<<ggrid, 256>>>(x, Wih_e, bih_e, Wih_d, bih_d);

    gru_scan<<<(NCL_ENC + NCL_DEC) * 4, NTHREADS>>>(
        Whh_e, bhh_e, Whh_d, bhh_d, out);
}